// round 8
// baseline (speedup 1.0000x reference)
#include <cuda_runtime.h>
#include <cuda_fp16.h>
#include <cstdint>

// ---------------- problem constants ----------------
#define HID   512
#define G4    2048
#define NAg   64
#define SEQ   16
#define BROWS 2048
#define TROWS 32768
#define NATTN 256
#define OUTHALF 16777216

#define AS 72              // smem tile row stride (halves)
#define TILE (128*AS)      // gemm_x stage tile (halves)
#define DS 132             // Dsm row stride (floats)

// k_steps stages (bytes): A 128x72 halves, B 256x72 halves, double buffered
#define SA_BYTES (128*AS*2)
#define SB_BYTES (256*AS*2)
#define STEP_SMEM (2*SA_BYTES + 2*SB_BYTES)   // 110592

// ---------------- device scratch ----------------
__device__ __half g_Wih_h[G4 * HID];   // PERMUTED rows: p = u*4+g
__device__ __half g_Whh_h[G4 * HID];   // PERMUTED rows: p = u*4+g
__device__ float  g_bsum[G4];          // permuted
__device__ __half g_Xh[(size_t)TROWS * HID];
__device__ __half g_Gx[(size_t)TROWS * G4];   // permuted cols
__device__ __half g_h16[2][BROWS * HID];      // h carry fp16, pre-reset-scaled
__device__ float  g_c0[BROWS * HID];          // initial c, pre-scaled
__device__ unsigned g_bar[16];

// ---------------- helpers ----------------
__device__ __forceinline__ float sigmoid_f(float x) {
    return __fdividef(1.f, 1.f + __expf(-x));
}
__device__ __forceinline__ float tanh_f(float x) {
    return 1.f - __fdividef(2.f, __expf(2.f * x) + 1.f);
}
__device__ __forceinline__ uint32_t smaddr(const void* p) {
    return (uint32_t)__cvta_generic_to_shared(p);
}
__device__ __forceinline__ void cpa16(uint32_t d, const void* s) {
    asm volatile("cp.async.ca.shared.global [%0], [%1], 16;\n" :: "r"(d), "l"(s));
}
__device__ __forceinline__ void cpa16_cg(uint32_t d, const void* s) {
    asm volatile("cp.async.cg.shared.global [%0], [%1], 16;\n" :: "r"(d), "l"(s));
}
#define CP_COMMIT asm volatile("cp.async.commit_group;\n")
#define CP_WAIT1  asm volatile("cp.async.wait_group 1;\n")
#define CP_WAIT0  asm volatile("cp.async.wait_group 0;\n")

__device__ __forceinline__ void mma16816(float* d, const uint32_t* a, uint32_t b0, uint32_t b1) {
    asm volatile(
        "mma.sync.aligned.m16n8k16.row.col.f32.f16.f16.f32 "
        "{%0,%1,%2,%3},{%4,%5,%6,%7},{%8,%9},{%0,%1,%2,%3};\n"
        : "+f"(d[0]), "+f"(d[1]), "+f"(d[2]), "+f"(d[3])
        : "r"(a[0]), "r"(a[1]), "r"(a[2]), "r"(a[3]), "r"(b0), "r"(b1));
}

// ---------------- prep kernels ----------------
// permuted row p = u*4+g  <->  source row g*512+u
__global__ void k_prep_weights(const float* __restrict__ Wih, const float* __restrict__ Whh,
                               const float* __restrict__ bih, const float* __restrict__ bhh) {
    int i = blockIdx.x * blockDim.x + threadIdx.x;
    if (i < G4 * HID) {
        int p = i >> 9, k = i & 511;
        int u = p >> 2, g = p & 3;
        size_t src = (size_t)(g * HID + u) * HID + k;
        g_Wih_h[i] = __float2half_rn(Wih[src]);
        g_Whh_h[i] = __float2half_rn(Whh[src]);
    }
    if (i < G4) {
        int u = i >> 2, g = i & 3;
        g_bsum[i] = bih[g * HID + u] + bhh[g * HID + u];
    }
}

__global__ void k_pack_x(const float* __restrict__ h_self, const float* __restrict__ h_inter) {
    int idx = blockIdx.x * blockDim.x + threadIdx.x;
    int t   = idx >> 20;
    int rem = idx & ((1 << 20) - 1);
    int j   = rem >> 9;
    int k   = rem & 511;
    int b   = ((j >> 6) << 4) + t;
    int a   = j & 63;
    float v;
    if (k < NATTN) v = h_self[((size_t)(b * NAg + a)) * (2 * NATTN) + NATTN + k];
    else           v = h_inter[((size_t)(b * NAg + a)) * (HID - NATTN) + (k - NATTN)];
    g_Xh[idx] = __float2half_rn(v);
}

__global__ void k_init_state(const float* __restrict__ hxs, const float* __restrict__ cxs,
                             const float* __restrict__ reset) {
    int i = blockIdx.x * blockDim.x + threadIdx.x;
    int j = i >> 9;
    int k = i & 511;
    int b = (j >> 6) << 4;
    int a = j & 63;
    size_t src = ((size_t)(b * NAg + a)) * HID + k;
    float rs = 1.f - reset[b];
    g_h16[0][i] = __float2half_rn(hxs[src] * rs);
    g_c0[i] = cxs[src] * rs;
    if (blockIdx.x == 0 && threadIdx.x < 16) g_bar[threadIdx.x] = 0;
}

// ---------------- x-path GEMM (known-good, 261us): Gx = Xh @ Wih_perm^T + b ----
__device__ __forceinline__ void mma_tile128(const __half* Asm, const __half* Bsm,
                                            float acc[4][4][4], int wm, int wn, int gid, int tig) {
#pragma unroll
    for (int kk = 0; kk < 4; kk++) {
        uint32_t af[4][4];
        int cb = kk * 16 + tig * 2;
#pragma unroll
        for (int mi = 0; mi < 4; mi++) {
            int r = wm * 64 + mi * 16 + gid;
            af[mi][0] = *(const uint32_t*)&Asm[r * AS + cb];
            af[mi][1] = *(const uint32_t*)&Asm[(r + 8) * AS + cb];
            af[mi][2] = *(const uint32_t*)&Asm[r * AS + cb + 8];
            af[mi][3] = *(const uint32_t*)&Asm[(r + 8) * AS + cb + 8];
        }
#pragma unroll
        for (int ni = 0; ni < 4; ni++) {
            int n = wn * 32 + ni * 8 + gid;
            uint32_t b0 = *(const uint32_t*)&Bsm[n * AS + cb];
            uint32_t b1 = *(const uint32_t*)&Bsm[n * AS + cb + 8];
#pragma unroll
            for (int mi = 0; mi < 4; mi++) mma16816(acc[mi][ni], af[mi], b0, b1);
        }
    }
}

__global__ __launch_bounds__(256, 2) void k_gemm_x() {
    extern __shared__ __half sm[];
    int tid  = threadIdx.x;
    int lane = tid & 31, warp = tid >> 5;
    int wm = warp >> 2, wn = warp & 3;
    int gid = lane >> 2, tig = lane & 3;
    int row0 = blockIdx.y * 128;
    int col0 = blockIdx.x * 128;

    float acc[4][4][4];
#pragma unroll
    for (int a = 0; a < 4; a++)
#pragma unroll
        for (int b = 0; b < 4; b++)
#pragma unroll
            for (int c = 0; c < 4; c++) acc[a][b][c] = 0.f;

    auto load = [&](int k0, int s) {
#pragma unroll
        for (int i = 0; i < 4; i++) {
            int e = tid + i * 256; int r = e >> 3, c = e & 7;
            cpa16(smaddr(&sm[s * TILE + r * AS + c * 8]),
                  &g_Xh[(size_t)(row0 + r) * HID + k0 + c * 8]);
        }
#pragma unroll
        for (int i = 0; i < 4; i++) {
            int e = tid + i * 256; int r = e >> 3, c = e & 7;
            cpa16(smaddr(&sm[(2 + s) * TILE + r * AS + c * 8]),
                  &g_Wih_h[(size_t)(col0 + r) * HID + k0 + c * 8]);
        }
    };

    load(0, 0); CP_COMMIT;
    for (int it = 0; it < 8; it++) {
        int s = it & 1;
        if (it < 7) { load((it + 1) * 64, s ^ 1); CP_COMMIT; CP_WAIT1; }
        else        { CP_WAIT0; }
        __syncthreads();
        mma_tile128(&sm[s * TILE], &sm[(2 + s) * TILE], acc, wm, wn, gid, tig);
        __syncthreads();
    }

#pragma unroll
    for (int mi = 0; mi < 4; mi++)
#pragma unroll
        for (int ni = 0; ni < 4; ni++) {
            int r   = row0 + wm * 64 + mi * 16 + gid;
            int col = col0 + wn * 32 + ni * 8 + tig * 2;
            float b0 = g_bsum[col], b1 = g_bsum[col + 1];
            *(__half2*)&g_Gx[(size_t)r * G4 + col] =
                __floats2half2_rn(acc[mi][ni][0] + b0, acc[mi][ni][1] + b1);
            *(__half2*)&g_Gx[(size_t)(r + 8) * G4 + col] =
                __floats2half2_rn(acc[mi][ni][2] + b0, acc[mi][ni][3] + b1);
        }
}

// ---------------- persistent legacy-HMMA recurrent scan ----------------
// grid (bu=8, bm=16) = 128 blocks <= 148 SMs -> exactly 1 CTA/SM, no sharing,
// no barrier-lockstep imbalance. Block tile: M=128 rows x N=256 permuted gate
// cols (64 units x 4 adjacent gates), K=512. Per-warp tile 64x64 (acc[4][8][4]).
// c carry in 32 regs/thread; h carry via gmem fp16 pre-scaled by next reset.
__global__ __launch_bounds__(256, 1) void k_steps(const float* __restrict__ reset,
                                                  float* __restrict__ out) {
    extern __shared__ __align__(1024) uint8_t smraw[];
    __half* As[2] = { (__half*)smraw, (__half*)(smraw + SA_BYTES) };
    __half* Bs[2] = { (__half*)(smraw + 2 * SA_BYTES),
                      (__half*)(smraw + 2 * SA_BYTES + SB_BYTES) };
    float*  Dsm = (float*)smraw;          // reused after mainloop (67584B <= 110592B)
    __shared__ float Rn[128];

    int tid  = threadIdx.x;
    int lane = tid & 31, warp = tid >> 5;
    int wm = warp >> 2, wn = warp & 3;    // wm 0..1, wn 0..3
    int gid = lane >> 2, tig = lane & 3;
    int bu = blockIdx.x, bm = blockIdx.y;
    int row0 = bm * 128;
    int ncol0 = bu * 256;                 // permuted col base == weight row base

    // c carry: instance (p,i): e=tid+i*256, r=e>>5, ul=e&31, U=bu*64+p*32+ul
    float c_carry[32];
#pragma unroll
    for (int p = 0; p < 2; p++)
#pragma unroll
        for (int i = 0; i < 16; i++) {
            int e = tid + i * 256;
            c_carry[p * 16 + i] =
                g_c0[(size_t)(row0 + (e >> 5)) * HID + bu * 64 + p * 32 + (e & 31)];
        }

    float* out_h = out;
    float* out_c = out + (size_t)OUTHALF;

    for (int t = 0; t < SEQ; t++) {
        if (tid < 128) {
            int row = row0 + tid;
            float r = (t + 1 < SEQ) ? reset[((row >> 6) << 4) + t + 1] : 0.f;
            Rn[tid] = 1.f - r;
        }

        float acc[4][8][4];
#pragma unroll
        for (int a = 0; a < 4; a++)
#pragma unroll
            for (int b = 0; b < 8; b++)
#pragma unroll
                for (int c = 0; c < 4; c++) acc[a][b][c] = 0.f;

        const __half* hsrc = g_h16[t & 1];
        __half* hnx = g_h16[(t + 1) & 1];

        auto load = [&](int kt, int s) {
            int k0 = kt * 64;
            // A: 128 rows x 64 halves (.cg: cross-block mutated within launch)
#pragma unroll
            for (int i = 0; i < 4; i++) {
                int e = tid + i * 256; int r = e >> 3, c = e & 7;
                cpa16_cg(smaddr(&As[s][r * AS + c * 8]),
                         &hsrc[(size_t)(row0 + r) * HID + k0 + c * 8]);
            }
            // B: 256 permuted weight rows x 64 halves (.ca: immutable weights)
#pragma unroll
            for (int i = 0; i < 8; i++) {
                int e = tid + i * 256; int r = e >> 3, c = e & 7;
                cpa16(smaddr(&Bs[s][r * AS + c * 8]),
                      &g_Whh_h[(size_t)(ncol0 + r) * HID + k0 + c * 8]);
            }
        };

        load(0, 0); CP_COMMIT;
        for (int it = 0; it < 8; it++) {
            int s = it & 1;
            if (it < 7) { load(it + 1, s ^ 1); CP_COMMIT; CP_WAIT1; }
            else        { CP_WAIT0; }
            __syncthreads();
#pragma unroll
            for (int kk = 0; kk < 4; kk++) {
                uint32_t af[4][4];
                int cb = kk * 16 + tig * 2;
#pragma unroll
                for (int mi = 0; mi < 4; mi++) {
                    int r = wm * 64 + mi * 16 + gid;
                    af[mi][0] = *(const uint32_t*)&As[s][r * AS + cb];
                    af[mi][1] = *(const uint32_t*)&As[s][(r + 8) * AS + cb];
                    af[mi][2] = *(const uint32_t*)&As[s][r * AS + cb + 8];
                    af[mi][3] = *(const uint32_t*)&As[s][(r + 8) * AS + cb + 8];
                }
#pragma unroll
                for (int ni = 0; ni < 8; ni++) {
                    int n = wn * 64 + ni * 8 + gid;
                    uint32_t b0 = *(const uint32_t*)&Bs[s][n * AS + cb];
                    uint32_t b1 = *(const uint32_t*)&Bs[s][n * AS + cb + 8];
#pragma unroll
                    for (int mi = 0; mi < 4; mi++) mma16816(acc[mi][ni], af[mi], b0, b1);
                }
            }
            __syncthreads();
        }

        // ---- epilogue: two passes over 128-col halves (Dsm reuses stage smem) ----
#pragma unroll
        for (int p = 0; p < 2; p++) {
            if ((wn >> 1) == p) {
#pragma unroll
                for (int mi = 0; mi < 4; mi++)
#pragma unroll
                    for (int ni = 0; ni < 8; ni++) {
                        int r   = wm * 64 + mi * 16 + gid;
                        int col = (wn & 1) * 64 + ni * 8 + tig * 2;
                        *(float2*)&Dsm[r * DS + col] =
                            make_float2(acc[mi][ni][0], acc[mi][ni][1]);
                        *(float2*)&Dsm[(r + 8) * DS + col] =
                            make_float2(acc[mi][ni][2], acc[mi][ni][3]);
                    }
            }
            __syncthreads();
#pragma unroll
            for (int i = 0; i < 16; i++) {
                int e = tid + i * 256;
                int r = e >> 5, ul = e & 31;
                int row = row0 + r;
                int U   = bu * 64 + p * 32 + ul;
                float4 d = *(const float4*)&Dsm[r * DS + ul * 4];
                const __half* gp = g_Gx + ((size_t)t * BROWS + row) * G4
                                 + bu * 256 + p * 128 + ul * 4;
                uint2 gu = *(const uint2*)gp;
                __half gx[4];
                *(uint2*)gx = gu;
                float xi = d.x + __half2float(gx[0]);
                float xf = d.y + __half2float(gx[1]);
                float xg = d.z + __half2float(gx[2]);
                float xo = d.w + __half2float(gx[3]);
                float ii = sigmoid_f(xi);
                float ff = sigmoid_f(xf);
                float gg = tanh_f(xg);
                float oo = sigmoid_f(xo);
                float c2 = ff * c_carry[p * 16 + i] + ii * gg;
                float h2 = oo * tanh_f(c2);
                int b = ((row >> 6) << 4) + t;
                int a = row & 63;
                size_t oidx = ((size_t)(b * NAg + a)) * HID + U;
                out_h[oidx] = h2;
                out_c[oidx] = c2;
                float rn = Rn[r];
                c_carry[p * 16 + i] = c2 * rn;
                hnx[(size_t)row * HID + U] = __float2half_rn(h2 * rn);
            }
            __syncthreads();
        }

        // ---- bounded cross-block barrier among the 8 bu-blocks of this row-group ----
        if (t < SEQ - 1) {
            if (tid == 0) {
                __threadfence();
                atomicAdd(&g_bar[bm], 1u);
                unsigned target = 8u * (unsigned)(t + 1);
                for (int it = 0; it < 2000000; it++) {          // watchdog, never hangs
                    if (atomicAdd(&g_bar[bm], 0u) >= target) break;
                    __nanosleep(64);
                }
                __threadfence();
            }
            __syncthreads();
        }
    }
}

// ---------------- launch ----------------
extern "C" void kernel_launch(void* const* d_in, const int* in_sizes, int n_in,
                              void* d_out, int out_size) {
    const float* h_self  = (const float*)d_in[0];
    const float* h_inter = (const float*)d_in[1];
    const float* hxs     = (const float*)d_in[2];
    const float* cxs     = (const float*)d_in[3];
    const float* reset   = (const float*)d_in[4];
    const float* Wih     = (const float*)d_in[5];
    const float* Whh     = (const float*)d_in[6];
    const float* bih     = (const float*)d_in[7];
    const float* bhh     = (const float*)d_in[8];
    float* out = (float*)d_out;

    const int gemm_smem = 4 * TILE * 2;     // 73728
    cudaFuncSetAttribute(k_gemm_x, cudaFuncAttributeMaxDynamicSharedMemorySize, gemm_smem);
    cudaFuncSetAttribute(k_steps,  cudaFuncAttributeMaxDynamicSharedMemorySize, STEP_SMEM);

    k_prep_weights<<<4096, 256>>>(Wih, Whh, bih, bhh);
    k_pack_x<<<65536, 256>>>(h_self, h_inter);
    k_init_state<<<4096, 256>>>(hxs, cxs, reset);
    k_gemm_x<<<dim3(16, 256), 256, gemm_smem>>>();
    k_steps<<<dim3(8, 16), 256, STEP_SMEM>>>(reset, out);
}